// round 1
// baseline (speedup 1.0000x reference)
#include <cuda_runtime.h>
#include <cuda_bf16.h>
#include <math.h>

// Problem constants (match reference)
#define MAXN 100000
#define MAXE 1200000
#define D    64
#define HID  128
#define C    40

// ---------------- device scratch (no allocs allowed) ----------------
__device__ int   d_deg[MAXN];
__device__ int   d_cursor[MAXN];
__device__ int   d_rowptr[MAXN + 1];
__device__ int   d_col[MAXE];
__device__ float d_agg1[(size_t)MAXN * D];        // 25.6 MB
__device__ float d_x1[(size_t)MAXN * HID];        // 51.2 MB
__device__ float d_y[(size_t)MAXN * C];           // 16 MB

// ---------------- CSR build ----------------
__global__ void k_init(int n) {
    int i = blockIdx.x * blockDim.x + threadIdx.x;
    if (i < n) { d_deg[i] = 0; d_cursor[i] = 0; }
}

__global__ void k_count(const int* __restrict__ adj, int e) {
    int i = blockIdx.x * blockDim.x + threadIdx.x;
    if (i < e) atomicAdd(&d_deg[adj[2 * i + 1]], 1);
}

// single-block scan over degrees -> rowptr (exclusive)
__global__ void k_scan(int n) {
    __shared__ int ssum[1024];
    int tid = threadIdx.x;
    int chunk = (n + 1023) >> 10;
    int s0 = tid * chunk;
    int s1 = s0 + chunk; if (s1 > n) s1 = n;
    int s = 0;
    for (int i = s0; i < s1; i++) s += d_deg[i];
    ssum[tid] = s;
    __syncthreads();
    for (int off = 1; off < 1024; off <<= 1) {
        int v = (tid >= off) ? ssum[tid - off] : 0;
        __syncthreads();
        ssum[tid] += v;
        __syncthreads();
    }
    int run = (tid == 0) ? 0 : ssum[tid - 1];
    for (int i = s0; i < s1; i++) { d_rowptr[i] = run; run += d_deg[i]; }
    if (tid == 1023) d_rowptr[n] = ssum[1023];
}

__global__ void k_scatter(const int* __restrict__ adj, int e) {
    int i = blockIdx.x * blockDim.x + threadIdx.x;
    if (i < e) {
        int s = adj[2 * i];
        int d = adj[2 * i + 1];
        int p = atomicAdd(&d_cursor[d], 1);
        d_col[d_rowptr[d] + p] = s;
    }
}

// ---------------- layer-1 aggregation: agg1[v] = h[v] + sum_{(u->v)} h[u] ----------------
__global__ void k_agg1(const float* __restrict__ h, int n) {
    int w = (blockIdx.x * blockDim.x + threadIdx.x) >> 5;
    int lane = threadIdx.x & 31;
    if (w >= n) return;
    const float2* h2 = (const float2*)h;
    float2 acc = h2[(size_t)w * 32 + lane];           // self-loop
    int beg = d_rowptr[w], end = d_rowptr[w + 1];
    int j = beg;
    for (; j + 1 < end; j += 2) {
        int s0 = d_col[j], s1 = d_col[j + 1];
        float2 v0 = h2[(size_t)s0 * 32 + lane];
        float2 v1 = h2[(size_t)s1 * 32 + lane];
        acc.x += v0.x; acc.y += v0.y;
        acc.x += v1.x; acc.y += v1.y;
    }
    if (j < end) {
        int s = d_col[j];
        float2 v = h2[(size_t)s * 32 + lane];
        acc.x += v.x; acc.y += v.y;
    }
    ((float2*)d_agg1)[(size_t)w * 32 + lane] = acc;
}

// ---------------- GEMM1: x1 = relu(agg1 @ W1 + b1)  (N x 64 @ 64 x 128) ----------------
__global__ void __launch_bounds__(256) k_gemm1(const float* __restrict__ W1,
                                               const float* __restrict__ b1, int n) {
    __shared__ float sAT[D][64];       // [k][node], 16 KB
    __shared__ float sW[D][HID];       // 32 KB   (total 48 KB exactly)
    int tid = threadIdx.x;

    // load W1 (64x128 floats = 2048 float4)
    {
        const float4* W4 = (const float4*)W1;
        float4* sW4 = (float4*)sW;
#pragma unroll
        for (int i = 0; i < 8; i++) sW4[tid + i * 256] = W4[tid + i * 256];
    }
    int node0 = blockIdx.x * 64;
    // load A tile transposed (64 nodes x 64 k)
#pragma unroll
    for (int it = 0; it < 4; it++) {
        int idx = tid + it * 256;
        int nodeL = idx >> 4;
        int k4 = idx & 15;
        int gn = node0 + nodeL;
        float4 v = make_float4(0.f, 0.f, 0.f, 0.f);
        if (gn < n) v = ((const float4*)d_agg1)[(size_t)gn * (D / 4) + k4];
        sAT[k4 * 4 + 0][nodeL] = v.x;
        sAT[k4 * 4 + 1][nodeL] = v.y;
        sAT[k4 * 4 + 2][nodeL] = v.z;
        sAT[k4 * 4 + 3][nodeL] = v.w;
    }
    __syncthreads();

    int ng = tid & 15;    // nodes ng*4 .. ng*4+3
    int og = tid >> 4;    // outs  og*8 .. og*8+7
    float acc[4][8];
#pragma unroll
    for (int i = 0; i < 4; i++)
#pragma unroll
        for (int j = 0; j < 8; j++) acc[i][j] = 0.f;

#pragma unroll
    for (int k = 0; k < D; k++) {
        float av[4];
#pragma unroll
        for (int i = 0; i < 4; i++) av[i] = sAT[k][ng * 4 + i];
        float4 w0 = *(const float4*)&sW[k][og * 8];
        float4 w1 = *(const float4*)&sW[k][og * 8 + 4];
        float wv[8] = {w0.x, w0.y, w0.z, w0.w, w1.x, w1.y, w1.z, w1.w};
#pragma unroll
        for (int i = 0; i < 4; i++)
#pragma unroll
            for (int j = 0; j < 8; j++) acc[i][j] += av[i] * wv[j];
    }

    float bb[8];
#pragma unroll
    for (int j = 0; j < 8; j++) bb[j] = b1[og * 8 + j];

#pragma unroll
    for (int i = 0; i < 4; i++) {
        int gn = node0 + ng * 4 + i;
        if (gn < n) {
            float4 o0, o1;
            o0.x = fmaxf(acc[i][0] + bb[0], 0.f);
            o0.y = fmaxf(acc[i][1] + bb[1], 0.f);
            o0.z = fmaxf(acc[i][2] + bb[2], 0.f);
            o0.w = fmaxf(acc[i][3] + bb[3], 0.f);
            o1.x = fmaxf(acc[i][4] + bb[4], 0.f);
            o1.y = fmaxf(acc[i][5] + bb[5], 0.f);
            o1.z = fmaxf(acc[i][6] + bb[6], 0.f);
            o1.w = fmaxf(acc[i][7] + bb[7], 0.f);
            ((float4*)d_x1)[(size_t)gn * (HID / 4) + og * 2 + 0] = o0;
            ((float4*)d_x1)[(size_t)gn * (HID / 4) + og * 2 + 1] = o1;
        }
    }
}

// ---------------- GEMM2: y = x1 @ W2   (N x 128 @ 128 x 40, bias deferred) ----------------
__global__ void __launch_bounds__(256) k_gemm2(const float* __restrict__ W2, int n) {
    __shared__ float sAT[32][129];      // [k-in-chunk][node], pad 129 -> conflict-free STS
    __shared__ float sW[HID][C];        // 20 KB
    int tid = threadIdx.x;
    for (int i = tid; i < HID * C; i += 256) ((float*)sW)[i] = W2[i];

    int node0 = blockIdx.x * 128;
    int og = tid & 7;     // outs og*5 .. og*5+4
    int ng = tid >> 3;    // nodes ng*4 .. ng*4+3 (128 nodes)
    float acc[4][5];
#pragma unroll
    for (int i = 0; i < 4; i++)
#pragma unroll
        for (int j = 0; j < 5; j++) acc[i][j] = 0.f;

    for (int kc = 0; kc < 4; kc++) {
        __syncthreads();
#pragma unroll
        for (int it = 0; it < 4; it++) {
            int idx = tid + it * 256;
            int nodeL = idx >> 3;
            int k4 = idx & 7;
            int gn = node0 + nodeL;
            float4 v = make_float4(0.f, 0.f, 0.f, 0.f);
            if (gn < n) v = ((const float4*)d_x1)[(size_t)gn * (HID / 4) + kc * 8 + k4];
            sAT[k4 * 4 + 0][nodeL] = v.x;
            sAT[k4 * 4 + 1][nodeL] = v.y;
            sAT[k4 * 4 + 2][nodeL] = v.z;
            sAT[k4 * 4 + 3][nodeL] = v.w;
        }
        __syncthreads();
#pragma unroll
        for (int k = 0; k < 32; k++) {
            float av[4];
#pragma unroll
            for (int i = 0; i < 4; i++) av[i] = sAT[k][ng * 4 + i];
            float wv[5];
#pragma unroll
            for (int j = 0; j < 5; j++) wv[j] = sW[kc * 32 + k][og * 5 + j];
#pragma unroll
            for (int i = 0; i < 4; i++)
#pragma unroll
                for (int j = 0; j < 5; j++) acc[i][j] += av[i] * wv[j];
        }
    }
#pragma unroll
    for (int i = 0; i < 4; i++) {
        int gn = node0 + ng * 4 + i;
        if (gn < n) {
#pragma unroll
            for (int j = 0; j < 5; j++)
                d_y[(size_t)gn * C + og * 5 + j] = acc[i][j];
        }
    }
}

// ---------------- layer-2 aggregation + bias + softmax ----------------
__global__ void k_agg2_softmax(const float* __restrict__ b2, float* __restrict__ out, int n) {
    int w = (blockIdx.x * blockDim.x + threadIdx.x) >> 5;
    int lane = threadIdx.x & 31;
    if (w >= n) return;
    const float* Y = d_y;
    bool hi = (lane < 8);
    float a = Y[(size_t)w * C + lane];                         // feats 0..31 (self)
    float b = hi ? Y[(size_t)w * C + 32 + lane] : 0.f;         // feats 32..39 (self)
    int beg = d_rowptr[w], end = d_rowptr[w + 1];
    int j = beg;
    for (; j + 1 < end; j += 2) {
        int s0 = d_col[j], s1 = d_col[j + 1];
        a += Y[(size_t)s0 * C + lane];
        a += Y[(size_t)s1 * C + lane];
        if (hi) {
            b += Y[(size_t)s0 * C + 32 + lane];
            b += Y[(size_t)s1 * C + 32 + lane];
        }
    }
    if (j < end) {
        int s = d_col[j];
        a += Y[(size_t)s * C + lane];
        if (hi) b += Y[(size_t)s * C + 32 + lane];
    }
    a += b2[lane];
    if (hi) b += b2[32 + lane];

    float m = a;
    float mb = hi ? b : -1e30f;
    m = fmaxf(m, mb);
#pragma unroll
    for (int off = 16; off; off >>= 1)
        m = fmaxf(m, __shfl_xor_sync(0xffffffffu, m, off));
    float ea = __expf(a - m);
    float eb = hi ? __expf(b - m) : 0.f;
    float s = ea + eb;
#pragma unroll
    for (int off = 16; off; off >>= 1)
        s += __shfl_xor_sync(0xffffffffu, s, off);
    float inv = 1.f / s;
    out[(size_t)w * C + lane] = ea * inv;
    if (hi) out[(size_t)w * C + 32 + lane] = eb * inv;
}

// ---------------- launch ----------------
extern "C" void kernel_launch(void* const* d_in, const int* in_sizes, int n_in,
                              void* d_out, int out_size) {
    const float* h   = (const float*)d_in[0];   // node_embeddings (N, 64)
    const int*   adj = (const int*)d_in[1];     // adjacency (E, 2)
    const float* W1  = (const float*)d_in[2];   // (64, 128)
    const float* b1  = (const float*)d_in[3];   // (128,)
    const float* W2  = (const float*)d_in[4];   // (128, 40)
    const float* b2  = (const float*)d_in[5];   // (40,)
    float* out = (float*)d_out;

    int n = in_sizes[0] / D;
    int e = in_sizes[1] / 2;
    if (n > MAXN) n = MAXN;
    if (e > MAXE) e = MAXE;

    // CSR build
    k_init<<<(n + 255) / 256, 256>>>(n);
    k_count<<<(e + 255) / 256, 256>>>(adj, e);
    k_scan<<<1, 1024>>>(n);
    k_scatter<<<(e + 255) / 256, 256>>>(adj, e);

    // layer 1: aggregate 64-dim, then dense+relu
    k_agg1<<<(n * 32 + 255) / 256, 256>>>(h, n);
    k_gemm1<<<(n + 63) / 64, 256>>>(W1, b1, n);

    // layer 2 reordered: transform first (to 40-dim), aggregate after
    k_gemm2<<<(n + 127) / 128, 256>>>(W2, n);
    k_agg2_softmax<<<(n * 32 + 255) / 256, 256>>>(b2, out, n);
}

// round 2
// speedup vs baseline: 1.0183x; 1.0183x over previous
#include <cuda_runtime.h>
#include <cuda_bf16.h>
#include <math.h>

#define MAXN 100000
#define MAXE 1200000
#define D    64
#define HID  128
#define C    40

// ---------------- device scratch ----------------
__device__ int   d_deg[MAXN];
__device__ int   d_cursor[MAXN];
__device__ int   d_rowptr[MAXN + 1];
__device__ int   d_col[MAXE];
__device__ float d_y[(size_t)MAXN * C];           // 16 MB (L2-resident)

// ---------------- CSR build ----------------
__global__ void k_init(int n) {
    int i = blockIdx.x * blockDim.x + threadIdx.x;
    if (i < n) { d_deg[i] = 0; d_cursor[i] = 0; }
}

__global__ void k_count(const int2* __restrict__ adj, int e) {
    int i = blockIdx.x * blockDim.x + threadIdx.x;
    if (i < e) atomicAdd(&d_deg[adj[i].y], 1);
}

__global__ void k_scan(int n) {
    __shared__ int ssum[1024];
    int tid = threadIdx.x;
    int chunk = (n + 1023) >> 10;
    int s0 = tid * chunk;
    int s1 = s0 + chunk; if (s1 > n) s1 = n;
    int s = 0;
    for (int i = s0; i < s1; i++) s += d_deg[i];
    ssum[tid] = s;
    __syncthreads();
    for (int off = 1; off < 1024; off <<= 1) {
        int v = (tid >= off) ? ssum[tid - off] : 0;
        __syncthreads();
        ssum[tid] += v;
        __syncthreads();
    }
    int run = (tid == 0) ? 0 : ssum[tid - 1];
    for (int i = s0; i < s1; i++) { d_rowptr[i] = run; run += d_deg[i]; }
    if (tid == 1023) d_rowptr[n] = ssum[1023];
}

__global__ void k_scatter(const int2* __restrict__ adj, int e) {
    int i = blockIdx.x * blockDim.x + threadIdx.x;
    if (i < e) {
        int2 ed = adj[i];
        int p = atomicAdd(&d_cursor[ed.y], 1);
        d_col[d_rowptr[ed.y] + p] = ed.x;
    }
}

// ---------------- fused: agg1 + GEMM1 + ReLU + GEMM2 -> d_y ----------------
// per block: 64 nodes, 256 threads
// smem floats: sW1[64*128]=8192 | sW2[128*40]=5120 | sAT[64][65]=4160 | sX[128][65]=8320
#define SM_W1 0
#define SM_W2 8192
#define SM_AT 13312
#define SM_X  17472
#define SM_TOTAL_F 25792   // 103168 bytes

__global__ void __launch_bounds__(256) k_fused(const float* __restrict__ h,
                                               const float* __restrict__ W1,
                                               const float* __restrict__ b1,
                                               const float* __restrict__ W2,
                                               int n) {
    extern __shared__ float smem[];
    float* sW1 = smem + SM_W1;
    float* sW2 = smem + SM_W2;
    float* sAT = smem + SM_AT;   // [k][node] stride 65
    float* sX  = smem + SM_X;    // [hid][node] stride 65

    int tid = threadIdx.x;
    int node0 = blockIdx.x * 64;

    // ---- load weights ----
    {
        const float4* W4 = (const float4*)W1;
        float4* s4 = (float4*)sW1;
#pragma unroll
        for (int i = 0; i < 8; i++) s4[tid + i * 256] = W4[tid + i * 256];
        const float4* V4 = (const float4*)W2;
        float4* t4 = (float4*)sW2;
#pragma unroll
        for (int i = 0; i < 5; i++) t4[tid + i * 256] = V4[tid + i * 256];
    }

    // ---- phase 0: gather-aggregate 64 nodes x 64 feats into sAT (transposed) ----
    {
        int w = tid >> 5, lane = tid & 31;
        const float2* h2 = (const float2*)h;
#pragma unroll
        for (int ii = 0; ii < 8; ii++) {
            int nodeL = w * 8 + ii;
            int gn = node0 + nodeL;
            float2 acc = make_float2(0.f, 0.f);
            if (gn < n) {
                acc = h2[(size_t)gn * 32 + lane];     // self-loop
                int beg = d_rowptr[gn], end = d_rowptr[gn + 1];
                int j = beg;
                for (; j + 1 < end; j += 2) {
                    int s0 = d_col[j], s1 = d_col[j + 1];
                    float2 v0 = h2[(size_t)s0 * 32 + lane];
                    float2 v1 = h2[(size_t)s1 * 32 + lane];
                    acc.x += v0.x + v1.x;
                    acc.y += v0.y + v1.y;
                }
                if (j < end) {
                    int s = d_col[j];
                    float2 v = h2[(size_t)s * 32 + lane];
                    acc.x += v.x; acc.y += v.y;
                }
            }
            sAT[(2 * lane) * 65 + nodeL] = acc.x;
            sAT[(2 * lane + 1) * 65 + nodeL] = acc.y;
        }
    }
    __syncthreads();

    // ---- phase 1: x1 = relu(agg @ W1 + b1), write transposed into sX ----
    {
        int ng = tid & 15;    // node group: nodes ng*4..+3
        int og = tid >> 4;    // hid group:  hid  og*8..+7
        float acc[4][8];
#pragma unroll
        for (int i = 0; i < 4; i++)
#pragma unroll
            for (int j = 0; j < 8; j++) acc[i][j] = 0.f;

#pragma unroll
        for (int k = 0; k < D; k++) {
            float av[4];
#pragma unroll
            for (int i = 0; i < 4; i++) av[i] = sAT[k * 65 + ng * 4 + i];
            float4 w0 = *(const float4*)&sW1[k * HID + og * 8];
            float4 w1 = *(const float4*)&sW1[k * HID + og * 8 + 4];
            float wv[8] = {w0.x, w0.y, w0.z, w0.w, w1.x, w1.y, w1.z, w1.w};
#pragma unroll
            for (int i = 0; i < 4; i++)
#pragma unroll
                for (int j = 0; j < 8; j++) acc[i][j] += av[i] * wv[j];
        }
        float bb[8];
#pragma unroll
        for (int j = 0; j < 8; j++) bb[j] = b1[og * 8 + j];
#pragma unroll
        for (int i = 0; i < 4; i++)
#pragma unroll
            for (int j = 0; j < 8; j++)
                sX[(og * 8 + j) * 65 + (ng * 4 + i)] = fmaxf(acc[i][j] + bb[j], 0.f);
    }
    __syncthreads();

    // ---- phase 2: y = x1 @ W2  (64 x 128 @ 128 x 40) ----
    {
        int og = tid & 7;     // class group: og*5..+4
        int ng = tid >> 3;    // node group: ng*2..+1
        float acc[2][5];
#pragma unroll
        for (int i = 0; i < 2; i++)
#pragma unroll
            for (int j = 0; j < 5; j++) acc[i][j] = 0.f;

#pragma unroll 8
        for (int k = 0; k < HID; k++) {
            float av[2];
            av[0] = sX[k * 65 + ng * 2];
            av[1] = sX[k * 65 + ng * 2 + 1];
            float wv[5];
#pragma unroll
            for (int j = 0; j < 5; j++) wv[j] = sW2[k * C + og * 5 + j];
#pragma unroll
            for (int i = 0; i < 2; i++)
#pragma unroll
                for (int j = 0; j < 5; j++) acc[i][j] += av[i] * wv[j];
        }
#pragma unroll
        for (int i = 0; i < 2; i++) {
            int gn = node0 + ng * 2 + i;
            if (gn < n) {
#pragma unroll
                for (int j = 0; j < 5; j++)
                    d_y[(size_t)gn * C + og * 5 + j] = acc[i][j];
            }
        }
    }
}

// ---------------- layer-2 aggregation + bias + softmax ----------------
__global__ void k_agg2_softmax(const float* __restrict__ b2, float* __restrict__ out, int n) {
    int w = (blockIdx.x * blockDim.x + threadIdx.x) >> 5;
    int lane = threadIdx.x & 31;
    if (w >= n) return;
    const float* Y = d_y;
    bool hi = (lane < 8);
    float a = Y[(size_t)w * C + lane];
    float b = hi ? Y[(size_t)w * C + 32 + lane] : 0.f;
    int beg = d_rowptr[w], end = d_rowptr[w + 1];
    int j = beg;
    for (; j + 1 < end; j += 2) {
        int s0 = d_col[j], s1 = d_col[j + 1];
        a += Y[(size_t)s0 * C + lane];
        a += Y[(size_t)s1 * C + lane];
        if (hi) {
            b += Y[(size_t)s0 * C + 32 + lane];
            b += Y[(size_t)s1 * C + 32 + lane];
        }
    }
    if (j < end) {
        int s = d_col[j];
        a += Y[(size_t)s * C + lane];
        if (hi) b += Y[(size_t)s * C + 32 + lane];
    }
    a += b2[lane];
    if (hi) b += b2[32 + lane];

    float m = hi ? fmaxf(a, b) : a;
#pragma unroll
    for (int off = 16; off; off >>= 1)
        m = fmaxf(m, __shfl_xor_sync(0xffffffffu, m, off));
    float ea = __expf(a - m);
    float eb = hi ? __expf(b - m) : 0.f;
    float s = ea + eb;
#pragma unroll
    for (int off = 16; off; off >>= 1)
        s += __shfl_xor_sync(0xffffffffu, s, off);
    float inv = 1.f / s;
    out[(size_t)w * C + lane] = ea * inv;
    if (hi) out[(size_t)w * C + 32 + lane] = eb * inv;
}

// ---------------- launch ----------------
extern "C" void kernel_launch(void* const* d_in, const int* in_sizes, int n_in,
                              void* d_out, int out_size) {
    const float* h   = (const float*)d_in[0];
    const int*   adj = (const int*)d_in[1];
    const float* W1  = (const float*)d_in[2];
    const float* b1  = (const float*)d_in[3];
    const float* W2  = (const float*)d_in[4];
    const float* b2  = (const float*)d_in[5];
    float* out = (float*)d_out;

    int n = in_sizes[0] / D;
    int e = in_sizes[1] / 2;
    if (n > MAXN) n = MAXN;
    if (e > MAXE) e = MAXE;

    static int smem_set = 0;
    // deterministic, idempotent attribute set (not a stream op; capture-safe)
    cudaFuncSetAttribute(k_fused, cudaFuncAttributeMaxDynamicSharedMemorySize,
                         SM_TOTAL_F * (int)sizeof(float));
    (void)smem_set;

    k_init<<<(n + 255) / 256, 256>>>(n);
    k_count<<<(e + 255) / 256, 256>>>((const int2*)adj, e);
    k_scan<<<1, 1024>>>(n);
    k_scatter<<<(e + 255) / 256, 256>>>((const int2*)adj, e);

    k_fused<<<(n + 63) / 64, 256, SM_TOTAL_F * sizeof(float)>>>(h, W1, b1, W2, n);
    k_agg2_softmax<<<(n * 32 + 255) / 256, 256>>>(b2, out, n);
}